// round 13
// baseline (speedup 1.0000x reference)
#include <cuda_runtime.h>
#include <cuda_bf16.h>
#include <math.h>
#include <stdint.h>

#define SEQ 4096
#define DIM 1024
typedef __nv_bfloat16 bf16;

// ---------------- scratch (device globals; no allocation allowed) ----------
__device__ __align__(16) bf16 g_hh[SEQ * DIM],  g_hl[SEQ * DIM];
__device__ __align__(16) bf16 g_wqh[DIM * DIM], g_wql[DIM * DIM];   // Wq^T hi/lo
__device__ __align__(16) bf16 g_wkh[DIM * DIM], g_wkl[DIM * DIM];   // Wk^T hi/lo
__device__ __align__(16) bf16 g_wvh[DIM * DIM], g_wvl[DIM * DIM];
__device__ __align__(16) bf16 g_mth[DIM * DIM], g_mtl[DIM * DIM];   // M^T = Wk^T Wq
__device__ __align__(16) bf16 g_qh[SEQ * DIM],  g_ql[SEQ * DIM];    // hM hi/lo
__device__ __align__(16) bf16 g_vth[(size_t)DIM * SEQ], g_vtl[(size_t)DIM * SEQ];  // V^T
__device__ float g_s[(size_t)SEQ * SEQ];
__device__ __align__(16) bf16 g_ph[(size_t)SEQ * SEQ], g_pl[(size_t)SEQ * SEQ];

// ---------------- PTX helpers ----------------------------------------------
__device__ __forceinline__ uint32_t smem_u32(const void* p) {
    uint32_t a;
    asm("{ .reg .u64 t; cvta.to.shared.u64 t, %1; cvt.u32.u64 %0, t; }" : "=r"(a) : "l"(p));
    return a;
}
__device__ __forceinline__ void cpa16(uint32_t s, const void* g) {
    asm volatile("cp.async.cg.shared.global [%0], [%1], 16;"
                 :: "r"(s), "l"(__cvta_generic_to_global(g)) : "memory");
}
#define CP_COMMIT() asm volatile("cp.async.commit_group;" ::: "memory")
#define CP_WAIT(n)  asm volatile("cp.async.wait_group %0;" :: "n"(n) : "memory")

__device__ __forceinline__ void ldm4(uint32_t a, uint32_t& r0, uint32_t& r1,
                                     uint32_t& r2, uint32_t& r3) {
    asm volatile("ldmatrix.sync.aligned.m8n8.x4.shared.b16 {%0,%1,%2,%3}, [%4];"
                 : "=r"(r0), "=r"(r1), "=r"(r2), "=r"(r3) : "r"(a));
}
__device__ __forceinline__ void mma_bf16(float* d, const uint32_t* a, const uint32_t* b) {
    asm volatile("mma.sync.aligned.m16n8k16.row.col.f32.bf16.bf16.f32 "
                 "{%0,%1,%2,%3}, {%4,%5,%6,%7}, {%8,%9}, {%0,%1,%2,%3};"
                 : "+f"(d[0]), "+f"(d[1]), "+f"(d[2]), "+f"(d[3])
                 : "r"(a[0]), "r"(a[1]), "r"(a[2]), "r"(a[3]), "r"(b[0]), "r"(b[1]));
}
__device__ __forceinline__ uint32_t pack2(float a, float b) {
    __nv_bfloat162 t = __floats2bfloat162_rn(a, b);
    return *reinterpret_cast<uint32_t*>(&t);
}
__device__ __forceinline__ void split1(float v, float& hi, float& lo) {
    bf16 h = __float2bfloat16_rn(v);
    hi = __bfloat162float(h);
    lo = v - hi;
}

// ---------------- embed + RMSNorm -> bf16 hi/lo -----------------------------
__global__ __launch_bounds__(256) void k_embed_rmsnorm(
    const int* __restrict__ x, const float* __restrict__ emb,
    const float* __restrict__ w, bf16* __restrict__ hh, bf16* __restrict__ hl)
{
    const int row = blockIdx.x;
    const int tok = x[row];
    const float4 v = reinterpret_cast<const float4*>(emb)[(size_t)tok * (DIM / 4) + threadIdx.x];

    float ss = v.x * v.x + v.y * v.y + v.z * v.z + v.w * v.w;
    #pragma unroll
    for (int o = 16; o > 0; o >>= 1) ss += __shfl_xor_sync(0xffffffffu, ss, o);
    __shared__ float ws[8];
    if ((threadIdx.x & 31) == 0) ws[threadIdx.x >> 5] = ss;
    __syncthreads();
    float tot = 0.f;
    #pragma unroll
    for (int i = 0; i < 8; i++) tot += ws[i];

    const float scale = rsqrtf(tot * (1.0f / DIM) + 1.1920929e-07f);
    const float4 wv = reinterpret_cast<const float4*>(w)[threadIdx.x];
    float o0 = v.x * scale * wv.x, o1 = v.y * scale * wv.y;
    float o2 = v.z * scale * wv.z, o3 = v.w * scale * wv.w;
    float h0, l0, h1, l1, h2, l2, h3, l3;
    split1(o0, h0, l0); split1(o1, h1, l1); split1(o2, h2, l2); split1(o3, h3, l3);
    uint2 uh = { pack2(h0, h1), pack2(h2, h3) };
    uint2 ul = { pack2(l0, l1), pack2(l2, l3) };
    reinterpret_cast<uint2*>(hh)[(size_t)row * (DIM / 4) + threadIdx.x] = uh;
    reinterpret_cast<uint2*>(hl)[(size_t)row * (DIM / 4) + threadIdx.x] = ul;
}

// ---------------- plain split fp32 -> bf16 hi/lo ----------------------------
__global__ __launch_bounds__(256) void k_split(
    const float* __restrict__ src, bf16* __restrict__ hi, bf16* __restrict__ lo)
{
    const int i = blockIdx.x * 256 + threadIdx.x;
    float4 v4 = reinterpret_cast<const float4*>(src)[i];
    float h0, l0, h1, l1, h2, l2, h3, l3;
    split1(v4.x, h0, l0); split1(v4.y, h1, l1); split1(v4.z, h2, l2); split1(v4.w, h3, l3);
    reinterpret_cast<uint2*>(hi)[i] = { pack2(h0, h1), pack2(h2, h3) };
    reinterpret_cast<uint2*>(lo)[i] = { pack2(l0, l1), pack2(l2, l3) };
}

// ---------------- transpose-split: fp32 [D,D] -> bf16 hi/lo transposed ------
// out[c][r] = src[r][c]. 32x32 tiles, 256 threads.
__global__ __launch_bounds__(256) void k_tsplit(
    const float* __restrict__ src, bf16* __restrict__ hi, bf16* __restrict__ lo)
{
    __shared__ float t[32][33];
    const int tr = blockIdx.y * 32, tc = blockIdx.x * 32;
    const int r = threadIdx.x >> 3, c4 = (threadIdx.x & 7) * 4;
    float4 v = *reinterpret_cast<const float4*>(src + (size_t)(tr + r) * DIM + tc + c4);
    t[r][c4] = v.x; t[r][c4 + 1] = v.y; t[r][c4 + 2] = v.z; t[r][c4 + 3] = v.w;
    __syncthreads();
    // write row oc of output = column oc of tile; 4 elems along r
    const int oc = threadIdx.x >> 3, og = (threadIdx.x & 7) * 4;
    float h0, l0, h1, l1, h2, l2, h3, l3;
    split1(t[og][oc],     h0, l0); split1(t[og + 1][oc], h1, l1);
    split1(t[og + 2][oc], h2, l2); split1(t[og + 3][oc], h3, l3);
    const size_t o = ((size_t)(tc + oc) * DIM + tr + og) >> 2;
    reinterpret_cast<uint2*>(hi)[o] = { pack2(h0, h1), pack2(h2, h3) };
    reinterpret_cast<uint2*>(lo)[o] = { pack2(l0, l1), pack2(l2, l3) };
}

// ---------------- 3xBF16 tensor-core GEMM -----------------------------------
// C[M,N] = (Ah+Al)[M,K] @ (Bh+Bl)[N,K]^T, both K-contiguous.
// 128x128 CTA, BK=32, 256 threads; warp grid 4(m) x 2(n), warp tile 32x64.
// 2-stage cp.async double buffer, ONE __syncthreads per iteration.
// EPI: 0 = fp32 C     1 = bf16 hi/lo split (O0=hi, O1=lo)     3 = SiLU fp32
#define STAGE_BYTES 40960
#define SMEM_BYTES  (2 * STAGE_BYTES)

__device__ __forceinline__ void load_stage(
    uint32_t sbase, const bf16* Ah, const bf16* Al, const bf16* Bh, const bf16* Bl,
    int bm, int bn, int K, int k0, int tid)
{
    #pragma unroll
    for (int i = 0; i < 2; i++) {
        const int ch = i * 256 + tid;
        const int row = ch >> 2, c = ch & 3;
        const uint32_t so = (uint32_t)row * 80 + (uint32_t)c * 16;
        const size_t goA = (size_t)(bm + row) * K + k0 + c * 8;
        const size_t goB = (size_t)(bn + row) * K + k0 + c * 8;
        cpa16(sbase + so,         Ah + goA);
        cpa16(sbase + 10240 + so, Al + goA);
        cpa16(sbase + 20480 + so, Bh + goB);
        cpa16(sbase + 30720 + so, Bl + goB);
    }
}

__device__ __forceinline__ void compute_stage(
    uint32_t sbase, int warp_m, int warp_n, int lane, float (&acc)[2][8][4])
{
    #pragma unroll
    for (int ks = 0; ks < 2; ks++) {
        uint32_t ahf[2][4], alf[2][4];
        #pragma unroll
        for (int mt = 0; mt < 2; mt++) {
            const uint32_t off =
                (uint32_t)(warp_m * 32 + mt * 16 + (lane & 15)) * 80 +
                (uint32_t)(ks * 16 + (lane >> 4) * 8) * 2;
            ldm4(sbase + off,         ahf[mt][0], ahf[mt][1], ahf[mt][2], ahf[mt][3]);
            ldm4(sbase + 10240 + off, alf[mt][0], alf[mt][1], alf[mt][2], alf[mt][3]);
        }
        uint32_t bhf[8][2], blf[8][2];
        #pragma unroll
        for (int j = 0; j < 4; j++) {
            const uint32_t off =
                (uint32_t)(warp_n * 64 + j * 16 + ((lane >> 4) & 1) * 8 + (lane & 7)) * 80 +
                (uint32_t)(ks * 16 + ((lane >> 3) & 1) * 8) * 2;
            uint32_t r0, r1, r2, r3;
            ldm4(sbase + 20480 + off, r0, r1, r2, r3);
            bhf[2 * j][0] = r0; bhf[2 * j][1] = r1;
            bhf[2 * j + 1][0] = r2; bhf[2 * j + 1][1] = r3;
            ldm4(sbase + 30720 + off, r0, r1, r2, r3);
            blf[2 * j][0] = r0; blf[2 * j][1] = r1;
            blf[2 * j + 1][0] = r2; blf[2 * j + 1][1] = r3;
        }
        #pragma unroll
        for (int mt = 0; mt < 2; mt++)
            #pragma unroll
            for (int nt = 0; nt < 8; nt++) {
                mma_bf16(acc[mt][nt], ahf[mt], bhf[nt]);   // hi*hi
                mma_bf16(acc[mt][nt], ahf[mt], blf[nt]);   // hi*lo
                mma_bf16(acc[mt][nt], alf[mt], bhf[nt]);   // lo*hi
            }
    }
}

template <int EPI>
__global__ __launch_bounds__(256) void k_mm(
    const bf16* __restrict__ Ah, const bf16* __restrict__ Al,
    const bf16* __restrict__ Bh, const bf16* __restrict__ Bl,
    void* __restrict__ O0, void* __restrict__ O1,
    int M, int N, int K)
{
    extern __shared__ char smem[];
    const uint32_t sb = smem_u32(smem);
    const int tid = threadIdx.x;
    const int wid = tid >> 5, lane = tid & 31;
    const int warp_m = wid & 3, warp_n = wid >> 2;
    const int bm = blockIdx.y * 128, bn = blockIdx.x * 128;

    float acc[2][8][4];
    #pragma unroll
    for (int a = 0; a < 2; a++)
        #pragma unroll
        for (int b = 0; b < 8; b++)
            #pragma unroll
            for (int c = 0; c < 4; c++) acc[a][b][c] = 0.f;

    const int niter = K >> 5;
    load_stage(sb, Ah, Al, Bh, Bl, bm, bn, K, 0, tid);
    CP_COMMIT();

    // canonical single-sync double-buffered mainloop:
    //   wait(buf it) -> sync (drains prev compute, makes data visible)
    //   -> issue loads for it+1 -> compute it
    for (int it = 0; it < niter; ++it) {
        CP_WAIT(0);
        __syncthreads();
        if (it + 1 < niter) {
            load_stage(sb + ((it + 1) & 1) * STAGE_BYTES, Ah, Al, Bh, Bl, bm, bn, K,
                       (it + 1) << 5, tid);
            CP_COMMIT();
        }
        compute_stage(sb + (it & 1) * STAGE_BYTES, warp_m, warp_n, lane, acc);
    }

    // epilogue
    const int mbase = bm + warp_m * 32;
    const int nb = bn + warp_n * 64;
    #pragma unroll
    for (int mt = 0; mt < 2; mt++)
        #pragma unroll
        for (int nt = 0; nt < 8; nt++) {
            const int r0 = mbase + mt * 16 + (lane >> 2);
            const int c0 = nb + nt * 8 + 2 * (lane & 3);
            float* d = acc[mt][nt];
            if (EPI == 0) {
                float* C = (float*)O0;
                *reinterpret_cast<float2*>(C + (size_t)r0 * N + c0)       = { d[0], d[1] };
                *reinterpret_cast<float2*>(C + (size_t)(r0 + 8) * N + c0) = { d[2], d[3] };
            } else if (EPI == 1) {
                bf16* Ch = (bf16*)O0; bf16* Cl = (bf16*)O1;
                float h0, l0, h1, l1, h2, l2, h3, l3;
                split1(d[0], h0, l0); split1(d[1], h1, l1);
                split1(d[2], h2, l2); split1(d[3], h3, l3);
                *reinterpret_cast<uint32_t*>(Ch + (size_t)r0 * N + c0)       = pack2(h0, h1);
                *reinterpret_cast<uint32_t*>(Cl + (size_t)r0 * N + c0)       = pack2(l0, l1);
                *reinterpret_cast<uint32_t*>(Ch + (size_t)(r0 + 8) * N + c0) = pack2(h2, h3);
                *reinterpret_cast<uint32_t*>(Cl + (size_t)(r0 + 8) * N + c0) = pack2(l2, l3);
            } else {  // SiLU fp32
                float* C = (float*)O0;
                float o0 = d[0] / (1.f + __expf(-d[0]));
                float o1 = d[1] / (1.f + __expf(-d[1]));
                float o2 = d[2] / (1.f + __expf(-d[2]));
                float o3 = d[3] / (1.f + __expf(-d[3]));
                *reinterpret_cast<float2*>(C + (size_t)r0 * N + c0)       = { o0, o1 };
                *reinterpret_cast<float2*>(C + (size_t)(r0 + 8) * N + c0) = { o2, o3 };
            }
        }
}

// ---------------- row softmax -> bf16 hi/lo probs ---------------------------
__global__ __launch_bounds__(256) void k_softmax(
    const float* __restrict__ s, bf16* __restrict__ ph, bf16* __restrict__ pl)
{
    const float* row = s + (size_t)blockIdx.x * SEQ;
    const int tid = threadIdx.x;
    __shared__ float red[8];

    float4 v[4];
    #pragma unroll
    for (int i = 0; i < 4; i++) v[i] = reinterpret_cast<const float4*>(row)[tid + i * 256];

    float m = -INFINITY;
    #pragma unroll
    for (int i = 0; i < 4; i++)
        m = fmaxf(m, fmaxf(fmaxf(v[i].x, v[i].y), fmaxf(v[i].z, v[i].w)));
    #pragma unroll
    for (int o = 16; o > 0; o >>= 1) m = fmaxf(m, __shfl_xor_sync(0xffffffffu, m, o));
    if ((tid & 31) == 0) red[tid >> 5] = m;
    __syncthreads();
    float rowmax = red[0];
    #pragma unroll
    for (int i = 1; i < 8; i++) rowmax = fmaxf(rowmax, red[i]);
    __syncthreads();

    float sum = 0.f;
    #pragma unroll
    for (int i = 0; i < 4; i++) {
        v[i].x = __expf(v[i].x - rowmax);
        v[i].y = __expf(v[i].y - rowmax);
        v[i].z = __expf(v[i].z - rowmax);
        v[i].w = __expf(v[i].w - rowmax);
        sum += v[i].x + v[i].y + v[i].z + v[i].w;
    }
    #pragma unroll
    for (int o = 16; o > 0; o >>= 1) sum += __shfl_xor_sync(0xffffffffu, sum, o);
    if ((tid & 31) == 0) red[tid >> 5] = sum;
    __syncthreads();
    float tot = 0.f;
    #pragma unroll
    for (int i = 0; i < 8; i++) tot += red[i];
    const float inv = 1.f / tot;

    uint2* oh = reinterpret_cast<uint2*>(ph + (size_t)blockIdx.x * SEQ);
    uint2* ol = reinterpret_cast<uint2*>(pl + (size_t)blockIdx.x * SEQ);
    #pragma unroll
    for (int i = 0; i < 4; i++) {
        float p0 = v[i].x * inv, p1 = v[i].y * inv, p2 = v[i].z * inv, p3 = v[i].w * inv;
        float h0, l0, h1, l1, h2, l2, h3, l3;
        split1(p0, h0, l0); split1(p1, h1, l1); split1(p2, h2, l2); split1(p3, h3, l3);
        oh[tid + i * 256] = { pack2(h0, h1), pack2(h2, h3) };
        ol[tid + i * 256] = { pack2(l0, l1), pack2(l2, l3) };
    }
}

// ---------------- launch ----------------------------------------------------
extern "C" void kernel_launch(void* const* d_in, const int* in_sizes, int n_in,
                              void* d_out, int out_size)
{
    const int*   x   = (const int*)d_in[0];
    const float* emb = (const float*)d_in[1];
    const float* w   = (const float*)d_in[2];
    const float* Wq  = (const float*)d_in[3];
    const float* Wk  = (const float*)d_in[4];
    const float* Wv  = (const float*)d_in[5];
    float* out = (float*)d_out;

    bf16 *hh, *hl, *wqh, *wql, *wkh, *wkl, *wvh, *wvl;
    bf16 *mth, *mtl, *qh, *ql, *vth, *vtl, *ph, *pl;
    float* s;
    cudaGetSymbolAddress((void**)&hh, g_hh);   cudaGetSymbolAddress((void**)&hl, g_hl);
    cudaGetSymbolAddress((void**)&wqh, g_wqh); cudaGetSymbolAddress((void**)&wql, g_wql);
    cudaGetSymbolAddress((void**)&wkh, g_wkh); cudaGetSymbolAddress((void**)&wkl, g_wkl);
    cudaGetSymbolAddress((void**)&wvh, g_wvh); cudaGetSymbolAddress((void**)&wvl, g_wvl);
    cudaGetSymbolAddress((void**)&mth, g_mth); cudaGetSymbolAddress((void**)&mtl, g_mtl);
    cudaGetSymbolAddress((void**)&qh, g_qh);   cudaGetSymbolAddress((void**)&ql, g_ql);
    cudaGetSymbolAddress((void**)&vth, g_vth); cudaGetSymbolAddress((void**)&vtl, g_vtl);
    cudaGetSymbolAddress((void**)&s, g_s);
    cudaGetSymbolAddress((void**)&ph, g_ph);   cudaGetSymbolAddress((void**)&pl, g_pl);

    cudaFuncSetAttribute(k_mm<0>, cudaFuncAttributeMaxDynamicSharedMemorySize, SMEM_BYTES);
    cudaFuncSetAttribute(k_mm<1>, cudaFuncAttributeMaxDynamicSharedMemorySize, SMEM_BYTES);
    cudaFuncSetAttribute(k_mm<3>, cudaFuncAttributeMaxDynamicSharedMemorySize, SMEM_BYTES);

    k_embed_rmsnorm<<<SEQ, 256>>>(x, emb, w, hh, hl);
    k_split<<<DIM * DIM / 1024, 256>>>(Wv, wvh, wvl);
    dim3 gt(DIM / 32, DIM / 32);
    k_tsplit<<<gt, 256>>>(Wq, wqh, wql);   // Wq^T hi/lo
    k_tsplit<<<gt, 256>>>(Wk, wkh, wkl);   // Wk^T hi/lo

    // M^T = Wk^T @ Wq :  C[j,d] = sum_r WkT[j,r] * WqT[d,r]   (NT form)
    dim3 gm(DIM / 128, DIM / 128);
    k_mm<1><<<gm, 256, SMEM_BYTES>>>(wkh, wkl, wqh, wql, mth, mtl, DIM, DIM, DIM);

    // hM = h @ M  (B = M^T, K-major)  -> bf16 hi/lo [SEQ, DIM]
    dim3 gq(DIM / 128, SEQ / 128);
    k_mm<1><<<gq, 256, SMEM_BYTES>>>(hh, hl, mth, mtl, qh, ql, SEQ, DIM, DIM);

    // V^T = Wv @ h^T -> bf16 hi/lo [DIM, SEQ]
    dim3 gv(SEQ / 128, DIM / 128);
    k_mm<1><<<gv, 256, SMEM_BYTES>>>(wvh, wvl, hh, hl, vth, vtl, DIM, SEQ, DIM);

    // scores = (hM) @ h^T  -> fp32 [SEQ, SEQ]
    dim3 gs(SEQ / 128, SEQ / 128);
    k_mm<0><<<gs, 256, SMEM_BYTES>>>(qh, ql, hh, hl, s, nullptr, SEQ, SEQ, DIM);

    k_softmax<<<SEQ, 256>>>(s, ph, pl);

    // out = SiLU(P @ V)  (B = V^T, n-major)  -> fp32 [SEQ, DIM]
    dim3 go(DIM / 128, SEQ / 128);
    k_mm<3><<<go, 256, SMEM_BYTES>>>(ph, pl, vth, vtl, out, nullptr, SEQ, DIM, SEQ);
}

// round 15
// speedup vs baseline: 1.1797x; 1.1797x over previous
#include <cuda_runtime.h>
#include <cuda_bf16.h>
#include <math.h>
#include <stdint.h>

#define SEQ 4096
#define DIM 1024
typedef __nv_bfloat16 bf16;

// ---------------- scratch (device globals; no allocation allowed) ----------
__device__ __align__(16) bf16 g_hh[SEQ * DIM],  g_hl[SEQ * DIM];
__device__ __align__(16) bf16 g_wqh[DIM * DIM], g_wql[DIM * DIM];   // Wq^T hi/lo
__device__ __align__(16) bf16 g_wkh[DIM * DIM], g_wkl[DIM * DIM];   // Wk^T hi/lo
__device__ __align__(16) bf16 g_wvh[DIM * DIM], g_wvl[DIM * DIM];
__device__ __align__(16) bf16 g_mth[DIM * DIM], g_mtl[DIM * DIM];   // M^T = Wk^T Wq
__device__ __align__(16) bf16 g_qh[SEQ * DIM],  g_ql[SEQ * DIM];    // hM hi/lo
__device__ __align__(16) bf16 g_vth[(size_t)DIM * SEQ], g_vtl[(size_t)DIM * SEQ];  // V^T
__device__ float g_s[(size_t)SEQ * SEQ];
__device__ __align__(16) bf16 g_ph[(size_t)SEQ * SEQ], g_pl[(size_t)SEQ * SEQ];

// ---------------- PTX helpers ----------------------------------------------
__device__ __forceinline__ uint32_t smem_u32(const void* p) {
    uint32_t a;
    asm("{ .reg .u64 t; cvta.to.shared.u64 t, %1; cvt.u32.u64 %0, t; }" : "=r"(a) : "l"(p));
    return a;
}
__device__ __forceinline__ void cpa16(uint32_t s, const void* g) {
    asm volatile("cp.async.ca.shared.global [%0], [%1], 16;"
                 :: "r"(s), "l"(__cvta_generic_to_global(g)) : "memory");
}
#define CP_COMMIT() asm volatile("cp.async.commit_group;" ::: "memory")
#define CP_WAIT(n)  asm volatile("cp.async.wait_group %0;" :: "n"(n) : "memory")

__device__ __forceinline__ void ldm4(uint32_t a, uint32_t& r0, uint32_t& r1,
                                     uint32_t& r2, uint32_t& r3) {
    asm volatile("ldmatrix.sync.aligned.m8n8.x4.shared.b16 {%0,%1,%2,%3}, [%4];"
                 : "=r"(r0), "=r"(r1), "=r"(r2), "=r"(r3) : "r"(a));
}
__device__ __forceinline__ void mma_bf16(float* d, const uint32_t* a, const uint32_t* b) {
    asm volatile("mma.sync.aligned.m16n8k16.row.col.f32.bf16.bf16.f32 "
                 "{%0,%1,%2,%3}, {%4,%5,%6,%7}, {%8,%9}, {%0,%1,%2,%3};"
                 : "+f"(d[0]), "+f"(d[1]), "+f"(d[2]), "+f"(d[3])
                 : "r"(a[0]), "r"(a[1]), "r"(a[2]), "r"(a[3]), "r"(b[0]), "r"(b[1]));
}
__device__ __forceinline__ uint32_t pack2(float a, float b) {
    __nv_bfloat162 t = __floats2bfloat162_rn(a, b);
    return *reinterpret_cast<uint32_t*>(&t);
}
__device__ __forceinline__ void split1(float v, float& hi, float& lo) {
    bf16 h = __float2bfloat16_rn(v);
    hi = __bfloat162float(h);
    lo = v - hi;
}

// ---------------- embed + RMSNorm -> bf16 hi/lo -----------------------------
__global__ __launch_bounds__(256) void k_embed_rmsnorm(
    const int* __restrict__ x, const float* __restrict__ emb,
    const float* __restrict__ w, bf16* __restrict__ hh, bf16* __restrict__ hl)
{
    const int row = blockIdx.x;
    const int tok = x[row];
    const float4 v = reinterpret_cast<const float4*>(emb)[(size_t)tok * (DIM / 4) + threadIdx.x];

    float ss = v.x * v.x + v.y * v.y + v.z * v.z + v.w * v.w;
    #pragma unroll
    for (int o = 16; o > 0; o >>= 1) ss += __shfl_xor_sync(0xffffffffu, ss, o);
    __shared__ float ws[8];
    if ((threadIdx.x & 31) == 0) ws[threadIdx.x >> 5] = ss;
    __syncthreads();
    float tot = 0.f;
    #pragma unroll
    for (int i = 0; i < 8; i++) tot += ws[i];

    const float scale = rsqrtf(tot * (1.0f / DIM) + 1.1920929e-07f);
    const float4 wv = reinterpret_cast<const float4*>(w)[threadIdx.x];
    float o0 = v.x * scale * wv.x, o1 = v.y * scale * wv.y;
    float o2 = v.z * scale * wv.z, o3 = v.w * scale * wv.w;
    float h0, l0, h1, l1, h2, l2, h3, l3;
    split1(o0, h0, l0); split1(o1, h1, l1); split1(o2, h2, l2); split1(o3, h3, l3);
    uint2 uh = { pack2(h0, h1), pack2(h2, h3) };
    uint2 ul = { pack2(l0, l1), pack2(l2, l3) };
    reinterpret_cast<uint2*>(hh)[(size_t)row * (DIM / 4) + threadIdx.x] = uh;
    reinterpret_cast<uint2*>(hl)[(size_t)row * (DIM / 4) + threadIdx.x] = ul;
}

// ---------------- plain split fp32 -> bf16 hi/lo ----------------------------
__global__ __launch_bounds__(256) void k_split(
    const float* __restrict__ src, bf16* __restrict__ hi, bf16* __restrict__ lo)
{
    const int i = blockIdx.x * 256 + threadIdx.x;
    float4 v4 = reinterpret_cast<const float4*>(src)[i];
    float h0, l0, h1, l1, h2, l2, h3, l3;
    split1(v4.x, h0, l0); split1(v4.y, h1, l1); split1(v4.z, h2, l2); split1(v4.w, h3, l3);
    reinterpret_cast<uint2*>(hi)[i] = { pack2(h0, h1), pack2(h2, h3) };
    reinterpret_cast<uint2*>(lo)[i] = { pack2(l0, l1), pack2(l2, l3) };
}

// ---------------- transpose-split x2: Wq and Wk in one launch ---------------
// out[c][r] = src[r][c]. 32x32 tiles, 256 threads. blockIdx.z selects matrix.
__global__ __launch_bounds__(256) void k_tsplit2(
    const float* __restrict__ srcq, bf16* __restrict__ hiq, bf16* __restrict__ loq,
    const float* __restrict__ srck, bf16* __restrict__ hik, bf16* __restrict__ lok)
{
    const float* src = (blockIdx.z == 0) ? srcq : srck;
    bf16* hi = (blockIdx.z == 0) ? hiq : hik;
    bf16* lo = (blockIdx.z == 0) ? loq : lok;
    __shared__ float t[32][33];
    const int tr = blockIdx.y * 32, tc = blockIdx.x * 32;
    const int r = threadIdx.x >> 3, c4 = (threadIdx.x & 7) * 4;
    float4 v = *reinterpret_cast<const float4*>(src + (size_t)(tr + r) * DIM + tc + c4);
    t[r][c4] = v.x; t[r][c4 + 1] = v.y; t[r][c4 + 2] = v.z; t[r][c4 + 3] = v.w;
    __syncthreads();
    const int oc = threadIdx.x >> 3, og = (threadIdx.x & 7) * 4;
    float h0, l0, h1, l1, h2, l2, h3, l3;
    split1(t[og][oc],     h0, l0); split1(t[og + 1][oc], h1, l1);
    split1(t[og + 2][oc], h2, l2); split1(t[og + 3][oc], h3, l3);
    const size_t o = ((size_t)(tc + oc) * DIM + tr + og) >> 2;
    reinterpret_cast<uint2*>(hi)[o] = { pack2(h0, h1), pack2(h2, h3) };
    reinterpret_cast<uint2*>(lo)[o] = { pack2(l0, l1), pack2(l2, l3) };
}

// ---------------- 3xBF16 tensor-core GEMM (round-6/10 core) -----------------
// C[M,N] = (Ah+Al)[M,K] @ (Bh+Bl)[N,K]^T, both K-contiguous.
// 128x128 CTA, BK=32, 256 threads; warp grid 4(m) x 2(n), warp tile 32x64.
// EPI: 0 = fp32 C     1 = bf16 hi/lo split (O0=hi, O1=lo)     3 = SiLU fp32
#define STAGE_BYTES 40960
#define SMEM_BYTES  (2 * STAGE_BYTES)

__device__ __forceinline__ void load_stage(
    uint32_t sbase, const bf16* Ah, const bf16* Al, const bf16* Bh, const bf16* Bl,
    int bm, int bn, int K, int k0, int tid)
{
    #pragma unroll
    for (int i = 0; i < 2; i++) {
        const int ch = i * 256 + tid;
        const int row = ch >> 2, c = ch & 3;
        const uint32_t so = (uint32_t)row * 80 + (uint32_t)c * 16;
        const size_t goA = (size_t)(bm + row) * K + k0 + c * 8;
        const size_t goB = (size_t)(bn + row) * K + k0 + c * 8;
        cpa16(sbase + so,         Ah + goA);
        cpa16(sbase + 10240 + so, Al + goA);
        cpa16(sbase + 20480 + so, Bh + goB);
        cpa16(sbase + 30720 + so, Bl + goB);
    }
}

__device__ __forceinline__ void compute_stage(
    uint32_t sbase, int warp_m, int warp_n, int lane, float (&acc)[2][8][4])
{
    #pragma unroll
    for (int ks = 0; ks < 2; ks++) {
        uint32_t ahf[2][4], alf[2][4];
        #pragma unroll
        for (int mt = 0; mt < 2; mt++) {
            const uint32_t off =
                (uint32_t)(warp_m * 32 + mt * 16 + (lane & 15)) * 80 +
                (uint32_t)(ks * 16 + (lane >> 4) * 8) * 2;
            ldm4(sbase + off,         ahf[mt][0], ahf[mt][1], ahf[mt][2], ahf[mt][3]);
            ldm4(sbase + 10240 + off, alf[mt][0], alf[mt][1], alf[mt][2], alf[mt][3]);
        }
        uint32_t bhf[8][2], blf[8][2];
        #pragma unroll
        for (int j = 0; j < 4; j++) {
            const uint32_t off =
                (uint32_t)(warp_n * 64 + j * 16 + ((lane >> 4) & 1) * 8 + (lane & 7)) * 80 +
                (uint32_t)(ks * 16 + ((lane >> 3) & 1) * 8) * 2;
            uint32_t r0, r1, r2, r3;
            ldm4(sbase + 20480 + off, r0, r1, r2, r3);
            bhf[2 * j][0] = r0; bhf[2 * j][1] = r1;
            bhf[2 * j + 1][0] = r2; bhf[2 * j + 1][1] = r3;
            ldm4(sbase + 30720 + off, r0, r1, r2, r3);
            blf[2 * j][0] = r0; blf[2 * j][1] = r1;
            blf[2 * j + 1][0] = r2; blf[2 * j + 1][1] = r3;
        }
        #pragma unroll
        for (int mt = 0; mt < 2; mt++)
            #pragma unroll
            for (int nt = 0; nt < 8; nt++) {
                mma_bf16(acc[mt][nt], ahf[mt], bhf[nt]);   // hi*hi
                mma_bf16(acc[mt][nt], ahf[mt], blf[nt]);   // hi*lo
                mma_bf16(acc[mt][nt], alf[mt], bhf[nt]);   // lo*hi
            }
    }
}

template <int EPI>
__global__ __launch_bounds__(256) void k_mm(
    const bf16* __restrict__ Ah, const bf16* __restrict__ Al,
    const bf16* __restrict__ Bh, const bf16* __restrict__ Bl,
    void* __restrict__ O0, void* __restrict__ O1,
    int M, int N, int K)
{
    extern __shared__ char smem[];
    const uint32_t sb = smem_u32(smem);
    const int tid = threadIdx.x;
    const int wid = tid >> 5, lane = tid & 31;
    const int warp_m = wid & 3, warp_n = wid >> 2;
    const int bm = blockIdx.y * 128, bn = blockIdx.x * 128;

    float acc[2][8][4];
    #pragma unroll
    for (int a = 0; a < 2; a++)
        #pragma unroll
        for (int b = 0; b < 8; b++)
            #pragma unroll
            for (int c = 0; c < 4; c++) acc[a][b][c] = 0.f;

    const int niter = K >> 5;
    load_stage(sb, Ah, Al, Bh, Bl, bm, bn, K, 0, tid);
    CP_COMMIT();

    int s = 0;
    for (int it = 0; it < niter; ++it) {
        if (it + 1 < niter) {
            load_stage(sb + (s ^ 1) * STAGE_BYTES, Ah, Al, Bh, Bl, bm, bn, K,
                       (it + 1) << 5, tid);
            CP_COMMIT();
            CP_WAIT(1);
        } else {
            CP_WAIT(0);
        }
        __syncthreads();
        compute_stage(sb + s * STAGE_BYTES, warp_m, warp_n, lane, acc);
        __syncthreads();
        s ^= 1;
    }

    // epilogue
    const int mbase = bm + warp_m * 32;
    const int nb = bn + warp_n * 64;
    #pragma unroll
    for (int mt = 0; mt < 2; mt++)
        #pragma unroll
        for (int nt = 0; nt < 8; nt++) {
            const int r0 = mbase + mt * 16 + (lane >> 2);
            const int c0 = nb + nt * 8 + 2 * (lane & 3);
            float* d = acc[mt][nt];
            if (EPI == 0) {
                float* C = (float*)O0;
                *reinterpret_cast<float2*>(C + (size_t)r0 * N + c0)       = { d[0], d[1] };
                *reinterpret_cast<float2*>(C + (size_t)(r0 + 8) * N + c0) = { d[2], d[3] };
            } else if (EPI == 1) {
                bf16* Ch = (bf16*)O0; bf16* Cl = (bf16*)O1;
                float h0, l0, h1, l1, h2, l2, h3, l3;
                split1(d[0], h0, l0); split1(d[1], h1, l1);
                split1(d[2], h2, l2); split1(d[3], h3, l3);
                *reinterpret_cast<uint32_t*>(Ch + (size_t)r0 * N + c0)       = pack2(h0, h1);
                *reinterpret_cast<uint32_t*>(Cl + (size_t)r0 * N + c0)       = pack2(l0, l1);
                *reinterpret_cast<uint32_t*>(Ch + (size_t)(r0 + 8) * N + c0) = pack2(h2, h3);
                *reinterpret_cast<uint32_t*>(Cl + (size_t)(r0 + 8) * N + c0) = pack2(l2, l3);
            } else {  // SiLU fp32
                float* C = (float*)O0;
                float o0 = d[0] / (1.f + __expf(-d[0]));
                float o1 = d[1] / (1.f + __expf(-d[1]));
                float o2 = d[2] / (1.f + __expf(-d[2]));
                float o3 = d[3] / (1.f + __expf(-d[3]));
                *reinterpret_cast<float2*>(C + (size_t)r0 * N + c0)       = { o0, o1 };
                *reinterpret_cast<float2*>(C + (size_t)(r0 + 8) * N + c0) = { o2, o3 };
            }
        }
}

// ---------------- row softmax -> bf16 hi/lo probs ---------------------------
__global__ __launch_bounds__(256) void k_softmax(
    const float* __restrict__ s, bf16* __restrict__ ph, bf16* __restrict__ pl)
{
    const float* row = s + (size_t)blockIdx.x * SEQ;
    const int tid = threadIdx.x;
    __shared__ float red[8];

    float4 v[4];
    #pragma unroll
    for (int i = 0; i < 4; i++) v[i] = reinterpret_cast<const float4*>(row)[tid + i * 256];

    float m = -INFINITY;
    #pragma unroll
    for (int i = 0; i < 4; i++)
        m = fmaxf(m, fmaxf(fmaxf(v[i].x, v[i].y), fmaxf(v[i].z, v[i].w)));
    #pragma unroll
    for (int o = 16; o > 0; o >>= 1) m = fmaxf(m, __shfl_xor_sync(0xffffffffu, m, o));
    if ((tid & 31) == 0) red[tid >> 5] = m;
    __syncthreads();
    float rowmax = red[0];
    #pragma unroll
    for (int i = 1; i < 8; i++) rowmax = fmaxf(rowmax, red[i]);
    __syncthreads();

    float sum = 0.f;
    #pragma unroll
    for (int i = 0; i < 4; i++) {
        v[i].x = __expf(v[i].x - rowmax);
        v[i].y = __expf(v[i].y - rowmax);
        v[i].z = __expf(v[i].z - rowmax);
        v[i].w = __expf(v[i].w - rowmax);
        sum += v[i].x + v[i].y + v[i].z + v[i].w;
    }
    #pragma unroll
    for (int o = 16; o > 0; o >>= 1) sum += __shfl_xor_sync(0xffffffffu, sum, o);
    if ((tid & 31) == 0) red[tid >> 5] = sum;
    __syncthreads();
    float tot = 0.f;
    #pragma unroll
    for (int i = 0; i < 8; i++) tot += red[i];
    const float inv = 1.f / tot;

    uint2* oh = reinterpret_cast<uint2*>(ph + (size_t)blockIdx.x * SEQ);
    uint2* ol = reinterpret_cast<uint2*>(pl + (size_t)blockIdx.x * SEQ);
    #pragma unroll
    for (int i = 0; i < 4; i++) {
        float p0 = v[i].x * inv, p1 = v[i].y * inv, p2 = v[i].z * inv, p3 = v[i].w * inv;
        float h0, l0, h1, l1, h2, l2, h3, l3;
        split1(p0, h0, l0); split1(p1, h1, l1); split1(p2, h2, l2); split1(p3, h3, l3);
        oh[tid + i * 256] = { pack2(h0, h1), pack2(h2, h3) };
        ol[tid + i * 256] = { pack2(l0, l1), pack2(l2, l3) };
    }
}

// ---------------- launch ----------------------------------------------------
extern "C" void kernel_launch(void* const* d_in, const int* in_sizes, int n_in,
                              void* d_out, int out_size)
{
    const int*   x   = (const int*)d_in[0];
    const float* emb = (const float*)d_in[1];
    const float* w   = (const float*)d_in[2];
    const float* Wq  = (const float*)d_in[3];
    const float* Wk  = (const float*)d_in[4];
    const float* Wv  = (const float*)d_in[5];
    float* out = (float*)d_out;

    bf16 *hh, *hl, *wqh, *wql, *wkh, *wkl, *wvh, *wvl;
    bf16 *mth, *mtl, *qh, *ql, *vth, *vtl, *ph, *pl;
    float* s;
    cudaGetSymbolAddress((void**)&hh, g_hh);   cudaGetSymbolAddress((void**)&hl, g_hl);
    cudaGetSymbolAddress((void**)&wqh, g_wqh); cudaGetSymbolAddress((void**)&wql, g_wql);
    cudaGetSymbolAddress((void**)&wkh, g_wkh); cudaGetSymbolAddress((void**)&wkl, g_wkl);
    cudaGetSymbolAddress((void**)&wvh, g_wvh); cudaGetSymbolAddress((void**)&wvl, g_wvl);
    cudaGetSymbolAddress((void**)&mth, g_mth); cudaGetSymbolAddress((void**)&mtl, g_mtl);
    cudaGetSymbolAddress((void**)&qh, g_qh);   cudaGetSymbolAddress((void**)&ql, g_ql);
    cudaGetSymbolAddress((void**)&vth, g_vth); cudaGetSymbolAddress((void**)&vtl, g_vtl);
    cudaGetSymbolAddress((void**)&s, g_s);
    cudaGetSymbolAddress((void**)&ph, g_ph);   cudaGetSymbolAddress((void**)&pl, g_pl);

    cudaFuncSetAttribute(k_mm<0>, cudaFuncAttributeMaxDynamicSharedMemorySize, SMEM_BYTES);
    cudaFuncSetAttribute(k_mm<1>, cudaFuncAttributeMaxDynamicSharedMemorySize, SMEM_BYTES);
    cudaFuncSetAttribute(k_mm<3>, cudaFuncAttributeMaxDynamicSharedMemorySize, SMEM_BYTES);

    k_embed_rmsnorm<<<SEQ, 256>>>(x, emb, w, hh, hl);
    k_split<<<DIM * DIM / 1024, 256>>>(Wv, wvh, wvl);
    dim3 gt(DIM / 32, DIM / 32, 2);
    k_tsplit2<<<gt, 256>>>(Wq, wqh, wql, Wk, wkh, wkl);   // Wq^T, Wk^T hi/lo

    // M^T = Wk^T @ Wq :  C[j,d] = sum_r WkT[j,r] * WqT[d,r]   (NT form)
    dim3 gm(DIM / 128, DIM / 128);
    k_mm<1><<<gm, 256, SMEM_BYTES>>>(wkh, wkl, wqh, wql, mth, mtl, DIM, DIM, DIM);

    // hM = h @ M  (B = M^T, K-major)  -> bf16 hi/lo [SEQ, DIM]
    dim3 gq(DIM / 128, SEQ / 128);
    k_mm<1><<<gq, 256, SMEM_BYTES>>>(hh, hl, mth, mtl, qh, ql, SEQ, DIM, DIM);

    // V^T = Wv @ h^T -> bf16 hi/lo [DIM, SEQ]
    dim3 gv(SEQ / 128, DIM / 128);
    k_mm<1><<<gv, 256, SMEM_BYTES>>>(wvh, wvl, hh, hl, vth, vtl, DIM, SEQ, DIM);

    // scores = (hM) @ h^T  -> fp32 [SEQ, SEQ]
    dim3 gs(SEQ / 128, SEQ / 128);
    k_mm<0><<<gs, 256, SMEM_BYTES>>>(qh, ql, hh, hl, s, nullptr, SEQ, SEQ, DIM);

    k_softmax<<<SEQ, 256>>>(s, ph, pl);

    // out = SiLU(P @ V)  (B = V^T, n-major)  -> fp32 [SEQ, DIM]
    dim3 go(DIM / 128, SEQ / 128);
    k_mm<3><<<go, 256, SMEM_BYTES>>>(ph, pl, vth, vtl, out, nullptr, SEQ, DIM, SEQ);
}

// round 16
// speedup vs baseline: 1.2086x; 1.0246x over previous
#include <cuda_runtime.h>
#include <cuda_bf16.h>
#include <math.h>
#include <stdint.h>

#define SEQ 4096
#define DIM 1024
typedef __nv_bfloat16 bf16;

// ---------------- scratch (device globals; no allocation allowed) ----------
__device__ __align__(16) bf16 g_hh[SEQ * DIM],  g_hl[SEQ * DIM];
__device__ __align__(16) bf16 g_wqh[DIM * DIM], g_wql[DIM * DIM];   // Wq^T hi/lo
__device__ __align__(16) bf16 g_wkh[DIM * DIM], g_wkl[DIM * DIM];   // Wk^T hi/lo
__device__ __align__(16) bf16 g_wvh[DIM * DIM], g_wvl[DIM * DIM];
__device__ __align__(16) bf16 g_mth[DIM * DIM], g_mtl[DIM * DIM];   // M^T = Wk^T Wq
__device__ __align__(16) bf16 g_qh[SEQ * DIM],  g_ql[SEQ * DIM];    // hM hi/lo
__device__ __align__(16) bf16 g_vth[(size_t)DIM * SEQ], g_vtl[(size_t)DIM * SEQ];  // V^T
__device__ float g_s[(size_t)SEQ * SEQ];   // scores; also split-K partials early
__device__ __align__(16) bf16 g_ph[(size_t)SEQ * SEQ], g_pl[(size_t)SEQ * SEQ];

// ---------------- PTX helpers ----------------------------------------------
__device__ __forceinline__ uint32_t smem_u32(const void* p) {
    uint32_t a;
    asm("{ .reg .u64 t; cvta.to.shared.u64 t, %1; cvt.u32.u64 %0, t; }" : "=r"(a) : "l"(p));
    return a;
}
__device__ __forceinline__ void cpa16(uint32_t s, const void* g) {
    asm volatile("cp.async.ca.shared.global [%0], [%1], 16;"
                 :: "r"(s), "l"(__cvta_generic_to_global(g)) : "memory");
}
#define CP_COMMIT() asm volatile("cp.async.commit_group;" ::: "memory")
#define CP_WAIT(n)  asm volatile("cp.async.wait_group %0;" :: "n"(n) : "memory")

__device__ __forceinline__ void ldm4(uint32_t a, uint32_t& r0, uint32_t& r1,
                                     uint32_t& r2, uint32_t& r3) {
    asm volatile("ldmatrix.sync.aligned.m8n8.x4.shared.b16 {%0,%1,%2,%3}, [%4];"
                 : "=r"(r0), "=r"(r1), "=r"(r2), "=r"(r3) : "r"(a));
}
__device__ __forceinline__ void mma_bf16(float* d, const uint32_t* a, const uint32_t* b) {
    asm volatile("mma.sync.aligned.m16n8k16.row.col.f32.bf16.bf16.f32 "
                 "{%0,%1,%2,%3}, {%4,%5,%6,%7}, {%8,%9}, {%0,%1,%2,%3};"
                 : "+f"(d[0]), "+f"(d[1]), "+f"(d[2]), "+f"(d[3])
                 : "r"(a[0]), "r"(a[1]), "r"(a[2]), "r"(a[3]), "r"(b[0]), "r"(b[1]));
}
__device__ __forceinline__ uint32_t pack2(float a, float b) {
    __nv_bfloat162 t = __floats2bfloat162_rn(a, b);
    return *reinterpret_cast<uint32_t*>(&t);
}
__device__ __forceinline__ void split1(float v, float& hi, float& lo) {
    bf16 h = __float2bfloat16_rn(v);
    hi = __bfloat162float(h);
    lo = v - hi;
}

// ---------------- embed + RMSNorm -> bf16 hi/lo -----------------------------
__global__ __launch_bounds__(256) void k_embed_rmsnorm(
    const int* __restrict__ x, const float* __restrict__ emb,
    const float* __restrict__ w, bf16* __restrict__ hh, bf16* __restrict__ hl)
{
    const int row = blockIdx.x;
    const int tok = x[row];
    const float4 v = reinterpret_cast<const float4*>(emb)[(size_t)tok * (DIM / 4) + threadIdx.x];

    float ss = v.x * v.x + v.y * v.y + v.z * v.z + v.w * v.w;
    #pragma unroll
    for (int o = 16; o > 0; o >>= 1) ss += __shfl_xor_sync(0xffffffffu, ss, o);
    __shared__ float ws[8];
    if ((threadIdx.x & 31) == 0) ws[threadIdx.x >> 5] = ss;
    __syncthreads();
    float tot = 0.f;
    #pragma unroll
    for (int i = 0; i < 8; i++) tot += ws[i];

    const float scale = rsqrtf(tot * (1.0f / DIM) + 1.1920929e-07f);
    const float4 wv = reinterpret_cast<const float4*>(w)[threadIdx.x];
    float o0 = v.x * scale * wv.x, o1 = v.y * scale * wv.y;
    float o2 = v.z * scale * wv.z, o3 = v.w * scale * wv.w;
    float h0, l0, h1, l1, h2, l2, h3, l3;
    split1(o0, h0, l0); split1(o1, h1, l1); split1(o2, h2, l2); split1(o3, h3, l3);
    uint2 uh = { pack2(h0, h1), pack2(h2, h3) };
    uint2 ul = { pack2(l0, l1), pack2(l2, l3) };
    reinterpret_cast<uint2*>(hh)[(size_t)row * (DIM / 4) + threadIdx.x] = uh;
    reinterpret_cast<uint2*>(hl)[(size_t)row * (DIM / 4) + threadIdx.x] = ul;
}

// ---------------- weight prep, one launch -----------------------------------
// z=0: Wq^T split   z=1: Wk^T split   z=2: Wv plain split. 32x32 tiles.
__global__ __launch_bounds__(256) void k_prep(
    const float* __restrict__ Wq, bf16* __restrict__ qh, bf16* __restrict__ ql,
    const float* __restrict__ Wk, bf16* __restrict__ kh, bf16* __restrict__ kl,
    const float* __restrict__ Wv, bf16* __restrict__ vh, bf16* __restrict__ vl)
{
    const int tr = blockIdx.y * 32, tc = blockIdx.x * 32;
    if (blockIdx.z == 2) {   // plain split, no transpose
        const int r = threadIdx.x >> 3, c4 = (threadIdx.x & 7) * 4;
        const size_t idx = ((size_t)(tr + r) * DIM + tc + c4) >> 2;
        float4 v = reinterpret_cast<const float4*>(Wv)[idx];
        float h0, l0, h1, l1, h2, l2, h3, l3;
        split1(v.x, h0, l0); split1(v.y, h1, l1); split1(v.z, h2, l2); split1(v.w, h3, l3);
        reinterpret_cast<uint2*>(vh)[idx] = { pack2(h0, h1), pack2(h2, h3) };
        reinterpret_cast<uint2*>(vl)[idx] = { pack2(l0, l1), pack2(l2, l3) };
        return;
    }
    const float* src = (blockIdx.z == 0) ? Wq : Wk;
    bf16* hi = (blockIdx.z == 0) ? qh : kh;
    bf16* lo = (blockIdx.z == 0) ? ql : kl;
    __shared__ float t[32][33];
    const int r = threadIdx.x >> 3, c4 = (threadIdx.x & 7) * 4;
    float4 v = *reinterpret_cast<const float4*>(src + (size_t)(tr + r) * DIM + tc + c4);
    t[r][c4] = v.x; t[r][c4 + 1] = v.y; t[r][c4 + 2] = v.z; t[r][c4 + 3] = v.w;
    __syncthreads();
    const int oc = threadIdx.x >> 3, og = (threadIdx.x & 7) * 4;
    float h0, l0, h1, l1, h2, l2, h3, l3;
    split1(t[og][oc],     h0, l0); split1(t[og + 1][oc], h1, l1);
    split1(t[og + 2][oc], h2, l2); split1(t[og + 3][oc], h3, l3);
    const size_t o = ((size_t)(tc + oc) * DIM + tr + og) >> 2;
    reinterpret_cast<uint2*>(hi)[o] = { pack2(h0, h1), pack2(h2, h3) };
    reinterpret_cast<uint2*>(lo)[o] = { pack2(l0, l1), pack2(l2, l3) };
}

// ---------------- split-K reduction: hi/lo = split(p0 + p1) -----------------
__global__ __launch_bounds__(256) void k_addsplit(
    const float* __restrict__ p0, const float* __restrict__ p1,
    bf16* __restrict__ hi, bf16* __restrict__ lo)
{
    const int i = blockIdx.x * 256 + threadIdx.x;  // float4 index
    float4 a = reinterpret_cast<const float4*>(p0)[i];
    float4 b = reinterpret_cast<const float4*>(p1)[i];
    float s0 = a.x + b.x, s1 = a.y + b.y, s2 = a.z + b.z, s3 = a.w + b.w;
    float h0, l0, h1, l1, h2, l2, h3, l3;
    split1(s0, h0, l0); split1(s1, h1, l1); split1(s2, h2, l2); split1(s3, h3, l3);
    reinterpret_cast<uint2*>(hi)[i] = { pack2(h0, h1), pack2(h2, h3) };
    reinterpret_cast<uint2*>(lo)[i] = { pack2(l0, l1), pack2(l2, l3) };
}

// ---------------- 3xBF16 tensor-core GEMM (round-6/10 core) -----------------
// C[M,N] = (Ah+Al)[M,K] @ (Bh+Bl)[N,K]^T, both K-contiguous, row stride Kstride.
// blockIdx.z selects a K-slice of length Klen (split-K); EPI=0 writes partials
// at O0 + z*M*N. 128x128 CTA, BK=32, 256 threads; warp tile 32x64.
// EPI: 0 = fp32 C     1 = bf16 hi/lo split (O0=hi, O1=lo)     3 = SiLU fp32
#define STAGE_BYTES 40960
#define SMEM_BYTES  (2 * STAGE_BYTES)

__device__ __forceinline__ void load_stage(
    uint32_t sbase, const bf16* Ah, const bf16* Al, const bf16* Bh, const bf16* Bl,
    int bm, int bn, int Kstride, int k0, int tid)
{
    #pragma unroll
    for (int i = 0; i < 2; i++) {
        const int ch = i * 256 + tid;
        const int row = ch >> 2, c = ch & 3;
        const uint32_t so = (uint32_t)row * 80 + (uint32_t)c * 16;
        const size_t goA = (size_t)(bm + row) * Kstride + k0 + c * 8;
        const size_t goB = (size_t)(bn + row) * Kstride + k0 + c * 8;
        cpa16(sbase + so,         Ah + goA);
        cpa16(sbase + 10240 + so, Al + goA);
        cpa16(sbase + 20480 + so, Bh + goB);
        cpa16(sbase + 30720 + so, Bl + goB);
    }
}

__device__ __forceinline__ void compute_stage(
    uint32_t sbase, int warp_m, int warp_n, int lane, float (&acc)[2][8][4])
{
    #pragma unroll
    for (int ks = 0; ks < 2; ks++) {
        uint32_t ahf[2][4], alf[2][4];
        #pragma unroll
        for (int mt = 0; mt < 2; mt++) {
            const uint32_t off =
                (uint32_t)(warp_m * 32 + mt * 16 + (lane & 15)) * 80 +
                (uint32_t)(ks * 16 + (lane >> 4) * 8) * 2;
            ldm4(sbase + off,         ahf[mt][0], ahf[mt][1], ahf[mt][2], ahf[mt][3]);
            ldm4(sbase + 10240 + off, alf[mt][0], alf[mt][1], alf[mt][2], alf[mt][3]);
        }
        uint32_t bhf[8][2], blf[8][2];
        #pragma unroll
        for (int j = 0; j < 4; j++) {
            const uint32_t off =
                (uint32_t)(warp_n * 64 + j * 16 + ((lane >> 4) & 1) * 8 + (lane & 7)) * 80 +
                (uint32_t)(ks * 16 + ((lane >> 3) & 1) * 8) * 2;
            uint32_t r0, r1, r2, r3;
            ldm4(sbase + 20480 + off, r0, r1, r2, r3);
            bhf[2 * j][0] = r0; bhf[2 * j][1] = r1;
            bhf[2 * j + 1][0] = r2; bhf[2 * j + 1][1] = r3;
            ldm4(sbase + 30720 + off, r0, r1, r2, r3);
            blf[2 * j][0] = r0; blf[2 * j][1] = r1;
            blf[2 * j + 1][0] = r2; blf[2 * j + 1][1] = r3;
        }
        #pragma unroll
        for (int mt = 0; mt < 2; mt++)
            #pragma unroll
            for (int nt = 0; nt < 8; nt++) {
                mma_bf16(acc[mt][nt], ahf[mt], bhf[nt]);   // hi*hi
                mma_bf16(acc[mt][nt], ahf[mt], blf[nt]);   // hi*lo
                mma_bf16(acc[mt][nt], alf[mt], bhf[nt]);   // lo*hi
            }
    }
}

template <int EPI>
__global__ __launch_bounds__(256) void k_mm(
    const bf16* __restrict__ Ah, const bf16* __restrict__ Al,
    const bf16* __restrict__ Bh, const bf16* __restrict__ Bl,
    void* __restrict__ O0, void* __restrict__ O1,
    int M, int N, int Klen, int Kstride)
{
    extern __shared__ char smem[];
    const uint32_t sb = smem_u32(smem);
    const int tid = threadIdx.x;
    const int wid = tid >> 5, lane = tid & 31;
    const int warp_m = wid & 3, warp_n = wid >> 2;
    const int bm = blockIdx.y * 128, bn = blockIdx.x * 128;

    // split-K slice offset (z=0 for normal launches)
    const size_t koff = (size_t)blockIdx.z * (size_t)Klen;
    Ah += koff; Al += koff; Bh += koff; Bl += koff;

    float acc[2][8][4];
    #pragma unroll
    for (int a = 0; a < 2; a++)
        #pragma unroll
        for (int b = 0; b < 8; b++)
            #pragma unroll
            for (int c = 0; c < 4; c++) acc[a][b][c] = 0.f;

    const int niter = Klen >> 5;
    load_stage(sb, Ah, Al, Bh, Bl, bm, bn, Kstride, 0, tid);
    CP_COMMIT();

    int s = 0;
    for (int it = 0; it < niter; ++it) {
        if (it + 1 < niter) {
            load_stage(sb + (s ^ 1) * STAGE_BYTES, Ah, Al, Bh, Bl, bm, bn, Kstride,
                       (it + 1) << 5, tid);
            CP_COMMIT();
            CP_WAIT(1);
        } else {
            CP_WAIT(0);
        }
        __syncthreads();
        compute_stage(sb + s * STAGE_BYTES, warp_m, warp_n, lane, acc);
        __syncthreads();
        s ^= 1;
    }

    // epilogue
    const int mbase = bm + warp_m * 32;
    const int nb = bn + warp_n * 64;
    #pragma unroll
    for (int mt = 0; mt < 2; mt++)
        #pragma unroll
        for (int nt = 0; nt < 8; nt++) {
            const int r0 = mbase + mt * 16 + (lane >> 2);
            const int c0 = nb + nt * 8 + 2 * (lane & 3);
            float* d = acc[mt][nt];
            if (EPI == 0) {
                float* C = (float*)O0 + (size_t)blockIdx.z * M * N;
                *reinterpret_cast<float2*>(C + (size_t)r0 * N + c0)       = { d[0], d[1] };
                *reinterpret_cast<float2*>(C + (size_t)(r0 + 8) * N + c0) = { d[2], d[3] };
            } else if (EPI == 1) {
                bf16* Ch = (bf16*)O0; bf16* Cl = (bf16*)O1;
                float h0, l0, h1, l1, h2, l2, h3, l3;
                split1(d[0], h0, l0); split1(d[1], h1, l1);
                split1(d[2], h2, l2); split1(d[3], h3, l3);
                *reinterpret_cast<uint32_t*>(Ch + (size_t)r0 * N + c0)       = pack2(h0, h1);
                *reinterpret_cast<uint32_t*>(Cl + (size_t)r0 * N + c0)       = pack2(l0, l1);
                *reinterpret_cast<uint32_t*>(Ch + (size_t)(r0 + 8) * N + c0) = pack2(h2, h3);
                *reinterpret_cast<uint32_t*>(Cl + (size_t)(r0 + 8) * N + c0) = pack2(l2, l3);
            } else {  // SiLU fp32
                float* C = (float*)O0;
                float o0 = d[0] / (1.f + __expf(-d[0]));
                float o1 = d[1] / (1.f + __expf(-d[1]));
                float o2 = d[2] / (1.f + __expf(-d[2]));
                float o3 = d[3] / (1.f + __expf(-d[3]));
                *reinterpret_cast<float2*>(C + (size_t)r0 * N + c0)       = { o0, o1 };
                *reinterpret_cast<float2*>(C + (size_t)(r0 + 8) * N + c0) = { o2, o3 };
            }
        }
}

// ---------------- row softmax -> bf16 hi/lo probs ---------------------------
__global__ __launch_bounds__(256) void k_softmax(
    const float* __restrict__ s, bf16* __restrict__ ph, bf16* __restrict__ pl)
{
    const float* row = s + (size_t)blockIdx.x * SEQ;
    const int tid = threadIdx.x;
    __shared__ float red[8];

    float4 v[4];
    #pragma unroll
    for (int i = 0; i < 4; i++) v[i] = reinterpret_cast<const float4*>(row)[tid + i * 256];

    float m = -INFINITY;
    #pragma unroll
    for (int i = 0; i < 4; i++)
        m = fmaxf(m, fmaxf(fmaxf(v[i].x, v[i].y), fmaxf(v[i].z, v[i].w)));
    #pragma unroll
    for (int o = 16; o > 0; o >>= 1) m = fmaxf(m, __shfl_xor_sync(0xffffffffu, m, o));
    if ((tid & 31) == 0) red[tid >> 5] = m;
    __syncthreads();
    float rowmax = red[0];
    #pragma unroll
    for (int i = 1; i < 8; i++) rowmax = fmaxf(rowmax, red[i]);
    __syncthreads();

    float sum = 0.f;
    #pragma unroll
    for (int i = 0; i < 4; i++) {
        v[i].x = __expf(v[i].x - rowmax);
        v[i].y = __expf(v[i].y - rowmax);
        v[i].z = __expf(v[i].z - rowmax);
        v[i].w = __expf(v[i].w - rowmax);
        sum += v[i].x + v[i].y + v[i].z + v[i].w;
    }
    #pragma unroll
    for (int o = 16; o > 0; o >>= 1) sum += __shfl_xor_sync(0xffffffffu, sum, o);
    if ((tid & 31) == 0) red[tid >> 5] = sum;
    __syncthreads();
    float tot = 0.f;
    #pragma unroll
    for (int i = 0; i < 8; i++) tot += red[i];
    const float inv = 1.f / tot;

    uint2* oh = reinterpret_cast<uint2*>(ph + (size_t)blockIdx.x * SEQ);
    uint2* ol = reinterpret_cast<uint2*>(pl + (size_t)blockIdx.x * SEQ);
    #pragma unroll
    for (int i = 0; i < 4; i++) {
        float p0 = v[i].x * inv, p1 = v[i].y * inv, p2 = v[i].z * inv, p3 = v[i].w * inv;
        float h0, l0, h1, l1, h2, l2, h3, l3;
        split1(p0, h0, l0); split1(p1, h1, l1); split1(p2, h2, l2); split1(p3, h3, l3);
        oh[tid + i * 256] = { pack2(h0, h1), pack2(h2, h3) };
        ol[tid + i * 256] = { pack2(l0, l1), pack2(l2, l3) };
    }
}

// ---------------- launch ----------------------------------------------------
extern "C" void kernel_launch(void* const* d_in, const int* in_sizes, int n_in,
                              void* d_out, int out_size)
{
    const int*   x   = (const int*)d_in[0];
    const float* emb = (const float*)d_in[1];
    const float* w   = (const float*)d_in[2];
    const float* Wq  = (const float*)d_in[3];
    const float* Wk  = (const float*)d_in[4];
    const float* Wv  = (const float*)d_in[5];
    float* out = (float*)d_out;

    bf16 *hh, *hl, *wqh, *wql, *wkh, *wkl, *wvh, *wvl;
    bf16 *mth, *mtl, *qh, *ql, *vth, *vtl, *ph, *pl;
    float* s;
    cudaGetSymbolAddress((void**)&hh, g_hh);   cudaGetSymbolAddress((void**)&hl, g_hl);
    cudaGetSymbolAddress((void**)&wqh, g_wqh); cudaGetSymbolAddress((void**)&wql, g_wql);
    cudaGetSymbolAddress((void**)&wkh, g_wkh); cudaGetSymbolAddress((void**)&wkl, g_wkl);
    cudaGetSymbolAddress((void**)&wvh, g_wvh); cudaGetSymbolAddress((void**)&wvl, g_wvl);
    cudaGetSymbolAddress((void**)&mth, g_mth); cudaGetSymbolAddress((void**)&mtl, g_mtl);
    cudaGetSymbolAddress((void**)&qh, g_qh);   cudaGetSymbolAddress((void**)&ql, g_ql);
    cudaGetSymbolAddress((void**)&vth, g_vth); cudaGetSymbolAddress((void**)&vtl, g_vtl);
    cudaGetSymbolAddress((void**)&s, g_s);
    cudaGetSymbolAddress((void**)&ph, g_ph);   cudaGetSymbolAddress((void**)&pl, g_pl);

    cudaFuncSetAttribute(k_mm<0>, cudaFuncAttributeMaxDynamicSharedMemorySize, SMEM_BYTES);
    cudaFuncSetAttribute(k_mm<1>, cudaFuncAttributeMaxDynamicSharedMemorySize, SMEM_BYTES);
    cudaFuncSetAttribute(k_mm<3>, cudaFuncAttributeMaxDynamicSharedMemorySize, SMEM_BYTES);

    k_embed_rmsnorm<<<SEQ, 256>>>(x, emb, w, hh, hl);
    dim3 gp(DIM / 32, DIM / 32, 3);
    k_prep<<<gp, 256>>>(Wq, wqh, wql, Wk, wkh, wkl, Wv, wvh, wvl);

    // M^T = Wk^T @ Wq, split-K x2 in one launch: z slice k in [z*512,(z+1)*512)
    // partials into g_s (dead until scores GEMM), then add+split -> mth/mtl
    dim3 gm(DIM / 128, DIM / 128, 2);
    k_mm<0><<<gm, 256, SMEM_BYTES>>>(wkh, wkl, wqh, wql, s, nullptr,
                                     DIM, DIM, DIM / 2, DIM);
    k_addsplit<<<DIM * DIM / 1024, 256>>>(s, s + (size_t)DIM * DIM, mth, mtl);

    // hM = h @ M  (B = M^T, K-major)  -> bf16 hi/lo [SEQ, DIM]
    dim3 gq(DIM / 128, SEQ / 128);
    k_mm<1><<<gq, 256, SMEM_BYTES>>>(hh, hl, mth, mtl, qh, ql, SEQ, DIM, DIM, DIM);

    // V^T = Wv @ h^T -> bf16 hi/lo [DIM, SEQ]
    dim3 gv(SEQ / 128, DIM / 128);
    k_mm<1><<<gv, 256, SMEM_BYTES>>>(wvh, wvl, hh, hl, vth, vtl, DIM, SEQ, DIM, DIM);

    // scores = (hM) @ h^T  -> fp32 [SEQ, SEQ]
    dim3 gs(SEQ / 128, SEQ / 128);
    k_mm<0><<<gs, 256, SMEM_BYTES>>>(qh, ql, hh, hl, s, nullptr, SEQ, SEQ, DIM, DIM);

    k_softmax<<<SEQ, 256>>>(s, ph, pl);

    // out = SiLU(P @ V)  (B = V^T, n-major)  -> fp32 [SEQ, DIM]
    dim3 go(DIM / 128, SEQ / 128);
    k_mm<3><<<go, 256, SMEM_BYTES>>>(ph, pl, vth, vtl, out, nullptr, SEQ, DIM, SEQ, SEQ);
}